// round 1
// baseline (speedup 1.0000x reference)
#include <cuda_runtime.h>

// Problem constants
#define BB 64
#define NN 512
#define DD 128       // input feature dim
#define MM 128       // projection dim
#define NEG_INF -1e9f

// Scratch (device globals; no allocation allowed)
__device__ float g_mk[BB * NN * MM];   // masked key projection, 16.8 MB
__device__ float g_dot[BB * NN];       // per-row mq . mk
__device__ float g_qsum[BB * MM];      // per-batch sum of mq

__global__ void zero_qsum_kernel() {
    int i = blockIdx.x * blockDim.x + threadIdx.x;
    if (i < BB * MM) g_qsum[i] = 0.0f;
}

__device__ __forceinline__ float warp_sum(float v) {
#pragma unroll
    for (int o = 16; o; o >>= 1) v += __shfl_xor_sync(0xffffffffu, v, o);
    return v;
}

__device__ __forceinline__ float warp_max(float v) {
#pragma unroll
    for (int o = 16; o; o >>= 1) v = fmaxf(v, __shfl_xor_sync(0xffffffffu, v, o));
    return v;
}

// ---------------------------------------------------------------------------
// Kernel A: fused Q/K projection GEMM + masked stats.
// Block = 256 threads (8 warps), each warp computes 4 rows of q and k (128
// cols each). A row values are held in registers and broadcast via SHFL.
// W is read via LDG (128 KB total; stays L1/L2 resident).
// Emits: g_mk (mask*k), g_dot (mq.mk per row), g_qsum (atomics, per batch).
// ---------------------------------------------------------------------------
__global__ __launch_bounds__(256) void qk_kernel(
    const float* __restrict__ A, const float* __restrict__ mask,
    const float* __restrict__ Wq, const float* __restrict__ bq,
    const float* __restrict__ Wk, const float* __restrict__ bk)
{
    const int warp = threadIdx.x >> 5;
    const int lane = threadIdx.x & 31;
    const int row0 = blockIdx.x * 32 + warp * 4;     // 32 rows per block
    const int b = (blockIdx.x * 32) / NN;            // 16 blocks per batch

    const float4* A4 = (const float4*)A;
    float4 a[4];
#pragma unroll
    for (int r = 0; r < 4; r++) a[r] = A4[(size_t)(row0 + r) * 32 + lane];

    float accq[4][4], acck[4][4];
#pragma unroll
    for (int r = 0; r < 4; r++)
#pragma unroll
        for (int e = 0; e < 4; e++) { accq[r][e] = 0.0f; acck[r][e] = 0.0f; }

    const float4* Wq4 = (const float4*)Wq;
    const float4* Wk4 = (const float4*)Wk;

    for (int kt = 0; kt < DD; kt += 4) {
        const int src = kt >> 2;
#pragma unroll
        for (int s = 0; s < 4; s++) {
            float4 wq = Wq4[(kt + s) * 32 + lane];
            float4 wk = Wk4[(kt + s) * 32 + lane];
#pragma unroll
            for (int r = 0; r < 4; r++) {
                float av;
                if      (s == 0) av = __shfl_sync(0xffffffffu, a[r].x, src);
                else if (s == 1) av = __shfl_sync(0xffffffffu, a[r].y, src);
                else if (s == 2) av = __shfl_sync(0xffffffffu, a[r].z, src);
                else             av = __shfl_sync(0xffffffffu, a[r].w, src);
                accq[r][0] = fmaf(av, wq.x, accq[r][0]);
                accq[r][1] = fmaf(av, wq.y, accq[r][1]);
                accq[r][2] = fmaf(av, wq.z, accq[r][2]);
                accq[r][3] = fmaf(av, wq.w, accq[r][3]);
                acck[r][0] = fmaf(av, wk.x, acck[r][0]);
                acck[r][1] = fmaf(av, wk.y, acck[r][1]);
                acck[r][2] = fmaf(av, wk.z, acck[r][2]);
                acck[r][3] = fmaf(av, wk.w, acck[r][3]);
            }
        }
    }

    // Epilogue: bias, mask, store mk, per-row dot, per-block q_sum partials.
    float4 bq4 = ((const float4*)bq)[lane];
    float4 bk4 = ((const float4*)bk)[lane];

    __shared__ float sQ[8][128];
    float qs0 = 0.f, qs1 = 0.f, qs2 = 0.f, qs3 = 0.f;

#pragma unroll
    for (int r = 0; r < 4; r++) {
        int row = row0 + r;
        float m = mask[row];
        float mq0 = m * (accq[r][0] + bq4.x);
        float mq1 = m * (accq[r][1] + bq4.y);
        float mq2 = m * (accq[r][2] + bq4.z);
        float mq3 = m * (accq[r][3] + bq4.w);
        float mk0 = m * (acck[r][0] + bk4.x);
        float mk1 = m * (acck[r][1] + bk4.y);
        float mk2 = m * (acck[r][2] + bk4.z);
        float mk3 = m * (acck[r][3] + bk4.w);

        ((float4*)g_mk)[(size_t)row * 32 + lane] = make_float4(mk0, mk1, mk2, mk3);

        float p = mq0 * mk0 + mq1 * mk1 + mq2 * mk2 + mq3 * mk3;
        p = warp_sum(p);
        if (lane == 0) g_dot[row] = p;

        qs0 += mq0; qs1 += mq1; qs2 += mq2; qs3 += mq3;
    }

    ((float4*)sQ[warp])[lane] = make_float4(qs0, qs1, qs2, qs3);
    __syncthreads();

    if (threadIdx.x < 128) {
        int c = threadIdx.x;
        float s = 0.f;
#pragma unroll
        for (int w = 0; w < 8; w++) s += sQ[w][c];
        atomicAdd(&g_qsum[b * MM + c], s);
    }
}

// ---------------------------------------------------------------------------
// Kernel B: one block per batch. agg -> euclidean normalize -> masked softmax
// -> attn out; then context = sum_i attn_i * mk_i.
// ---------------------------------------------------------------------------
__global__ __launch_bounds__(256) void attn_kernel(
    const float* __restrict__ mask, float* __restrict__ out)
{
    const int b = blockIdx.x;
    const int warp = threadIdx.x >> 5;
    const int lane = threadIdx.x & 31;
    const int tid = threadIdx.x;

    __shared__ float sAgg[NN];
    __shared__ float sRed[8];
    __shared__ float sCtx[8][128];

    float4 qs = ((const float4*)g_qsum)[b * 32 + lane];
    const float4* mk4 = (const float4*)g_mk;
    const size_t base = (size_t)b * NN;

    // agg_i = mask_i * (mk_i . q_sum - dot_i)
    for (int i = warp; i < NN; i += 8) {
        float4 mk = mk4[(base + i) * 32 + lane];
        float p = mk.x * qs.x + mk.y * qs.y + mk.z * qs.z + mk.w * qs.w;
        p = warp_sum(p);
        if (lane == 0) sAgg[i] = mask[base + i] * (p - g_dot[base + i]);
    }
    __syncthreads();

    // sum of squares -> norm
    float ss = 0.f;
    for (int i = tid; i < NN; i += 256) { float v = sAgg[i]; ss += v * v; }
    ss = warp_sum(ss);
    if (lane == 0) sRed[warp] = ss;
    __syncthreads();
    float tot = 0.f;
#pragma unroll
    for (int w = 0; w < 8; w++) tot += sRed[w];
    float inv = 1.0f / sqrtf(tot);

    // scores (+mask penalty), block max
    float mx = -INFINITY;
    for (int i = tid; i < NN; i += 256) {
        float sc = sAgg[i] * inv + (1.0f - mask[base + i]) * NEG_INF;
        sAgg[i] = sc;
        mx = fmaxf(mx, sc);
    }
    mx = warp_max(mx);
    __syncthreads();
    if (lane == 0) sRed[warp] = mx;
    __syncthreads();
    float M = -INFINITY;
#pragma unroll
    for (int w = 0; w < 8; w++) M = fmaxf(M, sRed[w]);

    // exp & sum
    float es = 0.f;
    for (int i = tid; i < NN; i += 256) {
        float e = expf(sAgg[i] - M);
        sAgg[i] = e;
        es += e;
    }
    es = warp_sum(es);
    __syncthreads();
    if (lane == 0) sRed[warp] = es;
    __syncthreads();
    float S = 0.f;
#pragma unroll
    for (int w = 0; w < 8; w++) S += sRed[w];

    // attn out
    for (int i = tid; i < NN; i += 256) {
        float at = sAgg[i] / S;
        sAgg[i] = at;
        out[base + i] = at;
    }
    __syncthreads();

    // context = sum_i attn_i * mk_i   (mk already includes mask)
    float cx = 0.f, cy = 0.f, cz = 0.f, cw = 0.f;
    for (int i = warp; i < NN; i += 8) {
        float at = sAgg[i];
        float4 mk = mk4[(base + i) * 32 + lane];
        cx = fmaf(at, mk.x, cx);
        cy = fmaf(at, mk.y, cy);
        cz = fmaf(at, mk.z, cz);
        cw = fmaf(at, mk.w, cw);
    }
    ((float4*)sCtx[warp])[lane] = make_float4(cx, cy, cz, cw);
    __syncthreads();
    if (tid < 128) {
        float s = 0.f;
#pragma unroll
        for (int w = 0; w < 8; w++) s += sCtx[w][tid];
        out[(size_t)BB * NN + (size_t)b * MM + tid] = s;
    }
}

extern "C" void kernel_launch(void* const* d_in, const int* in_sizes, int n_in,
                              void* d_out, int out_size)
{
    const float* A    = (const float*)d_in[0];  // atom_query [B,N,D]
    const float* mask = (const float*)d_in[1];  // [B,N,1]
    const float* Wq   = (const float*)d_in[2];  // [D,DIM]
    const float* bq   = (const float*)d_in[3];  // [DIM]
    const float* Wk   = (const float*)d_in[4];  // [D,DIM]
    const float* bk   = (const float*)d_in[5];  // [DIM]
    float* out = (float*)d_out;                 // attn [B*N] then context [B*DIM]

    zero_qsum_kernel<<<32, 256>>>();
    qk_kernel<<<(BB * NN) / 32, 256>>>(A, mask, Wq, bq, Wk, bk);
    attn_kernel<<<BB, 256>>>(mask, out);
}